// round 1
// baseline (speedup 1.0000x reference)
#include <cuda_runtime.h>

#define NUM_C 19
#define NUM_A 512          // feature channels
#define A4 (NUM_A / 4)     // float4 per row = 128
#define GRID1 512          // accumulation blocks
#define TPB1 128           // one float4 lane per thread

// Deterministic partial-sum scratch (no device-side allocation allowed).
__device__ float g_psums[(size_t)GRID1 * NUM_C * NUM_A]; // [g][c][a]
__device__ float g_pcnts[GRID1 * NUM_C];                 // [g][c]

__global__ void __launch_bounds__(TPB1) bars_accum_kernel(
    const float4* __restrict__ feat,   // (N, 128) float4
    const int*    __restrict__ labels, // (N,)
    const int*    __restrict__ ignore_ptr,
    int N)
{
    __shared__ float4 ssum[NUM_C * A4];  // 38912 B
    __shared__ float  scnt[NUM_C];

    const int t = threadIdx.x;

    #pragma unroll
    for (int i = t; i < NUM_C * A4; i += TPB1)
        ssum[i] = make_float4(0.f, 0.f, 0.f, 0.f);
    if (t < NUM_C) scnt[t] = 0.f;
    __syncthreads();

    const int ign  = *ignore_ptr;
    const int rows = (N + GRID1 - 1) / GRID1;
    const int r0   = blockIdx.x * rows;
    const int r1   = min(r0 + rows, N);

    int r = r0;
    // 8-row unrolled main loop: batch label loads, then batch predicated
    // feature loads (MLP), then smem RMWs.
    for (; r + 8 <= r1; r += 8) {
        int lab[8];
        #pragma unroll
        for (int j = 0; j < 8; j++) lab[j] = __ldg(&labels[r + j]);

        float4 f[8];
        #pragma unroll
        for (int j = 0; j < 8; j++)
            if (lab[j] != ign)
                f[j] = feat[(size_t)(r + j) * A4 + t];

        #pragma unroll
        for (int j = 0; j < 8; j++) {
            if (lab[j] != ign) {
                const int idx = lab[j] * A4 + t;
                float4 s = ssum[idx];
                s.x += f[j].x; s.y += f[j].y; s.z += f[j].z; s.w += f[j].w;
                ssum[idx] = s;
            }
        }
        if (t == 0) {
            #pragma unroll
            for (int j = 0; j < 8; j++)
                if (lab[j] != ign) scnt[lab[j]] += 1.f;
        }
    }
    // tail
    for (; r < r1; r++) {
        const int lab = __ldg(&labels[r]);
        if (lab != ign) {
            float4 f = feat[(size_t)r * A4 + t];
            const int idx = lab * A4 + t;
            float4 s = ssum[idx];
            s.x += f.x; s.y += f.y; s.z += f.z; s.w += f.w;
            ssum[idx] = s;
            if (t == 0) scnt[lab] += 1.f;
        }
    }
    __syncthreads();

    float4* out = reinterpret_cast<float4*>(g_psums) + (size_t)blockIdx.x * NUM_C * A4;
    #pragma unroll
    for (int i = t; i < NUM_C * A4; i += TPB1)
        out[i] = ssum[i];
    if (t < NUM_C)
        g_pcnts[blockIdx.x * NUM_C + t] = scnt[t];
}

// 19 blocks x 512 threads: block = class c, thread = channel a.
__global__ void __launch_bounds__(512) bars_finalize_kernel(float* __restrict__ out)
{
    const int c = blockIdx.x;
    const int a = threadIdx.x;

    __shared__ float sred[512];
    float cl = 0.f;
    for (int g = a; g < GRID1; g += 512)
        cl += g_pcnts[g * NUM_C + c];
    sred[a] = cl;
    __syncthreads();
    #pragma unroll
    for (int s = 256; s > 0; s >>= 1) {
        if (a < s) sred[a] += sred[a + s];
        __syncthreads();
    }
    const float cnt = sred[0];

    // Sum partials over g with 4 independent accumulators (break FADD chain,
    // keep >=4 loads in flight per thread).
    float s0 = 0.f, s1 = 0.f, s2 = 0.f, s3 = 0.f;
    const size_t stride = (size_t)NUM_C * NUM_A;
    const float* base = g_psums + (size_t)c * NUM_A + a;
    #pragma unroll 4
    for (int g = 0; g < GRID1; g += 4) {
        s0 += base[(size_t)(g + 0) * stride];
        s1 += base[(size_t)(g + 1) * stride];
        s2 += base[(size_t)(g + 2) * stride];
        s3 += base[(size_t)(g + 3) * stride];
    }
    const float sum = (s0 + s1) + (s2 + s3);
    const float amount = (cnt == 0.f) ? 1.f : cnt;

    out[c * NUM_A + a] = sum / amount;                    // mean (C, A)
    out[NUM_C * NUM_A + c * NUM_A + a] = cnt;             // sum_weight (C, A)
    if (a == 0)
        out[2 * NUM_C * NUM_A + c] = cnt;                 // class_dist (C,)
}

extern "C" void kernel_launch(void* const* d_in, const int* in_sizes, int n_in,
                              void* d_out, int out_size)
{
    const float4* feat   = (const float4*)d_in[0];
    const int*    labels = (const int*)d_in[1];
    const int*    ign    = (const int*)d_in[2];
    float*        out    = (float*)d_out;

    const int N = in_sizes[0] / NUM_A;

    bars_accum_kernel<<<GRID1, TPB1>>>(feat, labels, ign, N);
    bars_finalize_kernel<<<NUM_C, 512>>>(out);
}

// round 2
// speedup vs baseline: 1.0371x; 1.0371x over previous
#include <cuda_runtime.h>

#define NUM_C 19
#define NUM_A 512          // feature channels
#define A4 (NUM_A / 4)     // float4 per row = 128
#define GRID1 592          // 4 * 148 SMs -> one balanced wave at 4 blocks/SM
#define TPB1 128           // one float4 lane per thread

// Deterministic partial-sum scratch (no device-side allocation allowed).
__device__ float g_psums[(size_t)GRID1 * NUM_C * NUM_A]; // [g][c][a]  ~23 MB
__device__ float g_pcnts[GRID1 * NUM_C];                 // [g][c]

__global__ void __launch_bounds__(TPB1) bars_accum_kernel(
    const float4* __restrict__ feat,   // (N, 128) float4
    const int*    __restrict__ labels, // (N,)
    const int*    __restrict__ ignore_ptr,
    int N)
{
    __shared__ float4 ssum[NUM_C * A4];  // 38912 B -> 4 blocks/SM resident
    __shared__ float  scnt[NUM_C];

    const int t = threadIdx.x;

    #pragma unroll
    for (int i = t; i < NUM_C * A4; i += TPB1)
        ssum[i] = make_float4(0.f, 0.f, 0.f, 0.f);
    if (t < NUM_C) scnt[t] = 0.f;
    __syncthreads();

    const int ign  = *ignore_ptr;
    const int rows = (N + GRID1 - 1) / GRID1;
    const int r0   = blockIdx.x * rows;
    const int r1   = min(r0 + rows, N);

    int r = r0;
    // 8-row unrolled main loop: batch label loads, then batch predicated
    // feature loads (MLP=8), then smem RMWs.
    for (; r + 8 <= r1; r += 8) {
        int lab[8];
        #pragma unroll
        for (int j = 0; j < 8; j++) lab[j] = __ldg(&labels[r + j]);

        float4 f[8];
        #pragma unroll
        for (int j = 0; j < 8; j++)
            if (lab[j] != ign)
                f[j] = feat[(size_t)(r + j) * A4 + t];

        #pragma unroll
        for (int j = 0; j < 8; j++) {
            if (lab[j] != ign) {
                const int idx = lab[j] * A4 + t;
                float4 s = ssum[idx];
                s.x += f[j].x; s.y += f[j].y; s.z += f[j].z; s.w += f[j].w;
                ssum[idx] = s;
            }
        }
        if (t == 0) {
            #pragma unroll
            for (int j = 0; j < 8; j++)
                if (lab[j] != ign) scnt[lab[j]] += 1.f;
        }
    }
    // tail
    for (; r < r1; r++) {
        const int lab = __ldg(&labels[r]);
        if (lab != ign) {
            float4 f = feat[(size_t)r * A4 + t];
            const int idx = lab * A4 + t;
            float4 s = ssum[idx];
            s.x += f.x; s.y += f.y; s.z += f.z; s.w += f.w;
            ssum[idx] = s;
            if (t == 0) scnt[lab] += 1.f;
        }
    }
    __syncthreads();

    float4* pout = reinterpret_cast<float4*>(g_psums) + (size_t)blockIdx.x * NUM_C * A4;
    #pragma unroll
    for (int i = t; i < NUM_C * A4; i += TPB1)
        pout[i] = ssum[i];
    if (t < NUM_C)
        g_pcnts[blockIdx.x * NUM_C + t] = scnt[t];
}

// grid (NUM_C, 8), 64 threads: block = (class c, channel-group), thread = 1 channel.
// 152 blocks -> ~1 per SM, reads the 23 MB scratch chip-wide instead of on 19 SMs.
__global__ void __launch_bounds__(64) bars_finalize_kernel(float* __restrict__ out)
{
    const int c = blockIdx.x;
    const int a = blockIdx.y * 64 + threadIdx.x;
    const int t = threadIdx.x;

    // Per-class count: every block computes it redundantly (cheap: 592 floats).
    __shared__ float sred[64];
    float cl = 0.f;
    for (int g = t; g < GRID1; g += 64)
        cl += g_pcnts[g * NUM_C + c];
    sred[t] = cl;
    __syncthreads();
    #pragma unroll
    for (int s = 32; s > 0; s >>= 1) {
        if (t < s) sred[t] += sred[t + s];
        __syncthreads();
    }
    const float cnt = sred[0];

    // Sum partials over g with 4 independent accumulators.
    float s0 = 0.f, s1 = 0.f, s2 = 0.f, s3 = 0.f;
    const size_t stride = (size_t)NUM_C * NUM_A;
    const float* base = g_psums + (size_t)c * NUM_A + a;
    #pragma unroll 4
    for (int g = 0; g + 4 <= GRID1; g += 4) {
        s0 += base[(size_t)(g + 0) * stride];
        s1 += base[(size_t)(g + 1) * stride];
        s2 += base[(size_t)(g + 2) * stride];
        s3 += base[(size_t)(g + 3) * stride];
    }
    const float sum = (s0 + s1) + (s2 + s3);
    const float amount = (cnt == 0.f) ? 1.f : cnt;

    out[c * NUM_A + a] = sum / amount;                    // mean (C, A)
    out[NUM_C * NUM_A + c * NUM_A + a] = cnt;             // sum_weight (C, A)
    if (a == 0)
        out[2 * NUM_C * NUM_A + c] = cnt;                 // class_dist (C,)
}

extern "C" void kernel_launch(void* const* d_in, const int* in_sizes, int n_in,
                              void* d_out, int out_size)
{
    const float4* feat   = (const float4*)d_in[0];
    const int*    labels = (const int*)d_in[1];
    const int*    ign    = (const int*)d_in[2];
    float*        out    = (float*)d_out;

    const int N = in_sizes[0] / NUM_A;

    bars_accum_kernel<<<GRID1, TPB1>>>(feat, labels, ign, N);
    bars_finalize_kernel<<<dim3(NUM_C, 8), 64>>>(out);
}

// round 3
// speedup vs baseline: 1.1031x; 1.0637x over previous
#include <cuda_runtime.h>

#define NUM_C 19
#define NUM_A 512          // feature channels
#define A4 (NUM_A / 4)     // float4 per row = 128
#define GRID1 592          // 4 * 148 SMs -> one balanced wave at 4 blocks/SM
#define TPB1 128           // one float4 lane per thread

// Deterministic partial-sum scratch (no device-side allocation allowed).
__device__ float g_psums[(size_t)GRID1 * NUM_C * NUM_A]; // [g][c][a]  ~23 MB
__device__ float g_pcnts[GRID1 * NUM_C];                 // [g][c]

__global__ void __launch_bounds__(TPB1) bars_accum_kernel(
    const float4* __restrict__ feat,   // (N, 128) float4
    const int*    __restrict__ labels, // (N,)
    const int*    __restrict__ ignore_ptr,
    int N)
{
    __shared__ float4 ssum[NUM_C * A4];  // 38912 B -> 4 blocks/SM resident
    __shared__ float  scnt[NUM_C];

    const int t = threadIdx.x;

    #pragma unroll
    for (int i = t; i < NUM_C * A4; i += TPB1)
        ssum[i] = make_float4(0.f, 0.f, 0.f, 0.f);
    if (t < NUM_C) scnt[t] = 0.f;
    __syncthreads();

    const int ign  = *ignore_ptr;
    const int rows = (N + GRID1 - 1) / GRID1;
    const int r0   = blockIdx.x * rows;
    const int r1   = min(r0 + rows, N);

    int r = r0;
    // 8-row unrolled main loop: batch label loads, then batch predicated
    // feature loads (MLP=8), then smem RMWs.
    for (; r + 8 <= r1; r += 8) {
        int lab[8];
        #pragma unroll
        for (int j = 0; j < 8; j++) lab[j] = __ldg(&labels[r + j]);

        float4 f[8];
        #pragma unroll
        for (int j = 0; j < 8; j++)
            if (lab[j] != ign)
                f[j] = feat[(size_t)(r + j) * A4 + t];

        #pragma unroll
        for (int j = 0; j < 8; j++) {
            if (lab[j] != ign) {
                const int idx = lab[j] * A4 + t;
                float4 s = ssum[idx];
                s.x += f[j].x; s.y += f[j].y; s.z += f[j].z; s.w += f[j].w;
                ssum[idx] = s;
            }
        }
        if (t == 0) {
            #pragma unroll
            for (int j = 0; j < 8; j++)
                if (lab[j] != ign) scnt[lab[j]] += 1.f;
        }
    }
    // tail
    for (; r < r1; r++) {
        const int lab = __ldg(&labels[r]);
        if (lab != ign) {
            float4 f = feat[(size_t)r * A4 + t];
            const int idx = lab * A4 + t;
            float4 s = ssum[idx];
            s.x += f.x; s.y += f.y; s.z += f.z; s.w += f.w;
            ssum[idx] = s;
            if (t == 0) scnt[lab] += 1.f;
        }
    }
    __syncthreads();

    float4* pout = reinterpret_cast<float4*>(g_psums) + (size_t)blockIdx.x * NUM_C * A4;
    #pragma unroll
    for (int i = t; i < NUM_C * A4; i += TPB1)
        pout[i] = ssum[i];
    if (t < NUM_C)
        g_pcnts[blockIdx.x * NUM_C + t] = scnt[t];
}

// grid (NUM_C, 8) x 512 threads. Block = (class c, 64-channel group).
// Thread t: a4 = t%16 (float4 channel), gp = t/16 (one of 32 g-partitions).
// Each thread sums 18-19 float4 partials (independent addrs -> high MLP),
// then a 5-step smem tree folds the 32 g-partitions.
__global__ void __launch_bounds__(512) bars_finalize_kernel(float* __restrict__ out)
{
    const int c    = blockIdx.x;
    const int agrp = blockIdx.y;
    const int t    = threadIdx.x;
    const int a4   = t & 15;    // 0..15
    const int gp   = t >> 4;    // 0..31

    __shared__ float4 red[512];  // [gp][a4]
    __shared__ float  scnt;

    const float4* ps = reinterpret_cast<const float4*>(g_psums);
    const size_t stride = (size_t)NUM_C * A4;              // float4 per g-slab
    const size_t off    = (size_t)c * A4 + agrp * 16 + a4; // float4 within slab

    // Two independent accumulator streams over g = gp, gp+32, ...
    float4 s0 = make_float4(0.f, 0.f, 0.f, 0.f);
    float4 s1 = make_float4(0.f, 0.f, 0.f, 0.f);
    int g = gp;
    for (; g + 32 < GRID1; g += 64) {
        float4 v0 = ps[(size_t)g * stride + off];
        float4 v1 = ps[(size_t)(g + 32) * stride + off];
        s0.x += v0.x; s0.y += v0.y; s0.z += v0.z; s0.w += v0.w;
        s1.x += v1.x; s1.y += v1.y; s1.z += v1.z; s1.w += v1.w;
    }
    if (g < GRID1) {
        float4 v0 = ps[(size_t)g * stride + off];
        s0.x += v0.x; s0.y += v0.y; s0.z += v0.z; s0.w += v0.w;
    }
    s0.x += s1.x; s0.y += s1.y; s0.z += s1.z; s0.w += s1.w;
    red[gp * 16 + a4] = s0;

    // Warp 0 computes the class count concurrently (overlaps the loads above).
    if (t < 32) {
        float cl = 0.f;
        for (int gg = t; gg < GRID1; gg += 32)
            cl += g_pcnts[gg * NUM_C + c];
        #pragma unroll
        for (int o = 16; o > 0; o >>= 1)
            cl += __shfl_down_sync(0xFFFFFFFFu, cl, o);
        if (t == 0) scnt = cl;
    }
    __syncthreads();

    // Fold 32 g-partitions -> 1.
    #pragma unroll
    for (int s = 16; s > 0; s >>= 1) {
        if (gp < s) {
            float4 a = red[gp * 16 + a4];
            float4 b = red[(gp + s) * 16 + a4];
            a.x += b.x; a.y += b.y; a.z += b.z; a.w += b.w;
            red[gp * 16 + a4] = a;
        }
        __syncthreads();
    }

    if (t < 16) {
        const float cnt = scnt;
        const float inv = 1.f / ((cnt == 0.f) ? 1.f : cnt);
        float4 sum = red[a4];
        float4 mean = make_float4(sum.x * inv, sum.y * inv, sum.z * inv, sum.w * inv);

        float4* out4 = reinterpret_cast<float4*>(out);
        const int oidx = c * A4 + agrp * 16 + a4;
        out4[oidx] = mean;                                       // mean (C, A)
        out4[NUM_C * A4 + oidx] = make_float4(cnt, cnt, cnt, cnt); // sum_weight
        if (t == 0 && agrp == 0)
            out[2 * NUM_C * NUM_A + c] = cnt;                    // class_dist (C,)
    }
}

extern "C" void kernel_launch(void* const* d_in, const int* in_sizes, int n_in,
                              void* d_out, int out_size)
{
    const float4* feat   = (const float4*)d_in[0];
    const int*    labels = (const int*)d_in[1];
    const int*    ign    = (const int*)d_in[2];
    float*        out    = (float*)d_out;

    const int N = in_sizes[0] / NUM_A;

    bars_accum_kernel<<<GRID1, TPB1>>>(feat, labels, ign, N);
    bars_finalize_kernel<<<dim3(NUM_C, 8), 512>>>(out);
}

// round 4
// speedup vs baseline: 1.1270x; 1.0216x over previous
#include <cuda_runtime.h>

#define NUM_C 19
#define NUM_A 512          // feature channels
#define A4 (NUM_A / 4)     // float4 per row = 128
#define GRID1 592          // 4 * 148 SMs -> one balanced wave at 4 blocks/SM
#define TPB1 128           // one float4 lane per thread

// Deterministic partial-sum scratch (no device-side allocation allowed).
__device__ float g_psums[(size_t)GRID1 * NUM_C * NUM_A]; // [g][c][a]  ~23 MB
__device__ float g_pcnts[GRID1 * NUM_C];                 // [g][c]

__global__ void __launch_bounds__(TPB1) bars_accum_kernel(
    const float4* __restrict__ feat,   // (N, 128) float4
    const int*    __restrict__ labels, // (N,)
    const int*    __restrict__ ignore_ptr,
    int N)
{
    __shared__ float4 ssum[NUM_C * A4];  // 38912 B -> 4 blocks/SM resident
    __shared__ float  scnt[NUM_C];

    const int t = threadIdx.x;

    #pragma unroll
    for (int i = t; i < NUM_C * A4; i += TPB1)
        ssum[i] = make_float4(0.f, 0.f, 0.f, 0.f);
    if (t < NUM_C) scnt[t] = 0.f;
    __syncthreads();

    const int ign  = *ignore_ptr;
    const int rows = (N + GRID1 - 1) / GRID1;
    const int r0   = blockIdx.x * rows;
    const int r1   = min(r0 + rows, N);

    int r = r0;
    // 8-row unrolled main loop: batch label loads, then batch predicated
    // feature loads (MLP=8), then smem RMWs.
    for (; r + 8 <= r1; r += 8) {
        int lab[8];
        #pragma unroll
        for (int j = 0; j < 8; j++) lab[j] = __ldg(&labels[r + j]);

        float4 f[8];
        #pragma unroll
        for (int j = 0; j < 8; j++)
            if (lab[j] != ign)
                f[j] = feat[(size_t)(r + j) * A4 + t];

        #pragma unroll
        for (int j = 0; j < 8; j++) {
            if (lab[j] != ign) {
                const int idx = lab[j] * A4 + t;
                float4 s = ssum[idx];
                s.x += f[j].x; s.y += f[j].y; s.z += f[j].z; s.w += f[j].w;
                ssum[idx] = s;
            }
        }
        if (t == 0) {
            #pragma unroll
            for (int j = 0; j < 8; j++)
                if (lab[j] != ign) scnt[lab[j]] += 1.f;
        }
    }
    // tail
    for (; r < r1; r++) {
        const int lab = __ldg(&labels[r]);
        if (lab != ign) {
            float4 f = feat[(size_t)r * A4 + t];
            const int idx = lab * A4 + t;
            float4 s = ssum[idx];
            s.x += f.x; s.y += f.y; s.z += f.z; s.w += f.w;
            ssum[idx] = s;
            if (t == 0) scnt[lab] += 1.f;
        }
    }
    __syncthreads();

    float4* pout = reinterpret_cast<float4*>(g_psums) + (size_t)blockIdx.x * NUM_C * A4;
    #pragma unroll
    for (int i = t; i < NUM_C * A4; i += TPB1)
        pout[i] = ssum[i];
    if (t < NUM_C)
        g_pcnts[blockIdx.x * NUM_C + t] = scnt[t];
}

// grid (NUM_C, 8) x 512 threads. Block = (class c, 64-channel group).
// Thread t: a4 = t&15 (float4 channel), gp = t>>4 (one of 32 g-partitions).
// Fixed trip count (18 + 1 predicated) -> fully unrolled, 4 accumulator
// streams, ~18 independent LDG.128 in flight per thread.
__global__ void __launch_bounds__(512) bars_finalize_kernel(float* __restrict__ out)
{
    const int c    = blockIdx.x;
    const int agrp = blockIdx.y;
    const int t    = threadIdx.x;
    const int a4   = t & 15;    // 0..15
    const int gp   = t >> 4;    // 0..31
    const int warp = t >> 5;    // 0..15
    const int lane = t & 31;

    __shared__ float4 red[512];      // [gp][a4]
    __shared__ float  wcnt[16];      // per-warp count partials

    const float4* ps = reinterpret_cast<const float4*>(g_psums);
    const size_t stride = (size_t)NUM_C * A4;              // float4 per g-slab
    const size_t off    = (size_t)c * A4 + agrp * 16 + a4; // float4 within slab

    // ---- per-class count, fully parallel (each thread <=2 loads) ----
    {
        int g0 = warp * 32 + lane;                // 0..511
        float cl = g_pcnts[g0 * NUM_C + c];
        if (g0 + 512 < GRID1) cl += g_pcnts[(g0 + 512) * NUM_C + c];
        #pragma unroll
        for (int o = 16; o > 0; o >>= 1)
            cl += __shfl_down_sync(0xFFFFFFFFu, cl, o);
        if (lane == 0) wcnt[warp] = cl;
    }

    // ---- main partial-sum reduction: g = gp + 32*k ----
    float4 acc0 = make_float4(0.f, 0.f, 0.f, 0.f);
    float4 acc1 = make_float4(0.f, 0.f, 0.f, 0.f);
    float4 acc2 = make_float4(0.f, 0.f, 0.f, 0.f);
    float4 acc3 = make_float4(0.f, 0.f, 0.f, 0.f);
    const float4* base = ps + off + (size_t)gp * stride;
    #pragma unroll
    for (int k = 0; k < 18; k += 4) {          // 592/32 = 18.5
        float4 v0 = base[(size_t)(k + 0) * 32 * stride];
        float4 v1 = base[(size_t)(k + 1) * 32 * stride];
        float4 v2 = (k + 2 < 18) ? base[(size_t)(k + 2) * 32 * stride]
                                 : make_float4(0.f, 0.f, 0.f, 0.f);
        float4 v3 = (k + 3 < 18) ? base[(size_t)(k + 3) * 32 * stride]
                                 : make_float4(0.f, 0.f, 0.f, 0.f);
        acc0.x += v0.x; acc0.y += v0.y; acc0.z += v0.z; acc0.w += v0.w;
        acc1.x += v1.x; acc1.y += v1.y; acc1.z += v1.z; acc1.w += v1.w;
        acc2.x += v2.x; acc2.y += v2.y; acc2.z += v2.z; acc2.w += v2.w;
        acc3.x += v3.x; acc3.y += v3.y; acc3.z += v3.z; acc3.w += v3.w;
    }
    if (gp < GRID1 - 18 * 32) {                // extra slab g = gp + 576
        float4 v = base[(size_t)18 * 32 * stride];
        acc0.x += v.x; acc0.y += v.y; acc0.z += v.z; acc0.w += v.w;
    }
    acc0.x += acc1.x; acc0.y += acc1.y; acc0.z += acc1.z; acc0.w += acc1.w;
    acc2.x += acc3.x; acc2.y += acc3.y; acc2.z += acc3.z; acc2.w += acc3.w;
    acc0.x += acc2.x; acc0.y += acc2.y; acc0.z += acc2.z; acc0.w += acc2.w;
    red[gp * 16 + a4] = acc0;
    __syncthreads();

    // Fold 32 g-partitions -> 1.
    #pragma unroll
    for (int s = 16; s > 0; s >>= 1) {
        if (gp < s) {
            float4 a = red[gp * 16 + a4];
            float4 b = red[(gp + s) * 16 + a4];
            a.x += b.x; a.y += b.y; a.z += b.z; a.w += b.w;
            red[gp * 16 + a4] = a;
        }
        __syncthreads();
    }

    if (t < 16) {
        float cnt = 0.f;
        #pragma unroll
        for (int w = 0; w < 16; w++) cnt += wcnt[w];
        const float inv = 1.f / ((cnt == 0.f) ? 1.f : cnt);
        float4 sum = red[a4];
        float4 mean = make_float4(sum.x * inv, sum.y * inv, sum.z * inv, sum.w * inv);

        float4* out4 = reinterpret_cast<float4*>(out);
        const int oidx = c * A4 + agrp * 16 + a4;
        out4[oidx] = mean;                                         // mean (C, A)
        out4[NUM_C * A4 + oidx] = make_float4(cnt, cnt, cnt, cnt); // sum_weight
        if (t == 0 && agrp == 0)
            out[2 * NUM_C * NUM_A + c] = cnt;                      // class_dist (C,)
    }
}

extern "C" void kernel_launch(void* const* d_in, const int* in_sizes, int n_in,
                              void* d_out, int out_size)
{
    const float4* feat   = (const float4*)d_in[0];
    const int*    labels = (const int*)d_in[1];
    const int*    ign    = (const int*)d_in[2];
    float*        out    = (float*)d_out;

    const int N = in_sizes[0] / NUM_A;

    bars_accum_kernel<<<GRID1, TPB1>>>(feat, labels, ign, N);
    bars_finalize_kernel<<<dim3(NUM_C, 8), 512>>>(out);
}

// round 5
// speedup vs baseline: 1.2399x; 1.1003x over previous
#include <cuda_runtime.h>

#define NUM_C 19
#define NUM_A 512          // feature channels
#define A4 (NUM_A / 4)     // float4 per row = 128
#define GRID1 592          // 4 * 148 SMs -> one balanced wave at 4 blocks/SM
#define TPB1 128           // one float4 lane per thread

// Deterministic partial-sum scratch (no device-side allocation allowed).
__device__ float g_psums[(size_t)GRID1 * NUM_C * NUM_A]; // [g][c][a]  ~23 MB
__device__ float g_pcnts[GRID1 * NUM_C];                 // [g][c]

// ---- 8-row batch helpers (software pipeline) ----
#define LOAD_BATCH(RR, LAB, F)                                              \
    do {                                                                    \
        _Pragma("unroll")                                                   \
        for (int j = 0; j < 8; j++) LAB[j] = __ldg(&labels[(RR) + j]);      \
        _Pragma("unroll")                                                   \
        for (int j = 0; j < 8; j++)                                         \
            if (LAB[j] != ign)                                              \
                F[j] = feat[(size_t)((RR) + j) * A4 + t];                   \
    } while (0)

#define RMW_BATCH(LAB, F)                                                   \
    do {                                                                    \
        _Pragma("unroll")                                                   \
        for (int j = 0; j < 8; j++) {                                       \
            if (LAB[j] != ign) {                                            \
                const int idx = LAB[j] * A4 + t;                            \
                float4 s = ssum[idx];                                       \
                s.x += F[j].x; s.y += F[j].y; s.z += F[j].z; s.w += F[j].w; \
                ssum[idx] = s;                                              \
            }                                                               \
        }                                                                   \
        if (lane == 0) {                                                    \
            _Pragma("unroll")                                               \
            for (int j = 0; j < 2; j++) {                                   \
                const int jj = warp + 4 * j;                                \
                if (LAB[jj] != ign) scnt[warp][LAB[jj]] += 1.f;             \
            }                                                               \
        }                                                                   \
    } while (0)

__global__ void __launch_bounds__(TPB1, 4) bars_accum_kernel(
    const float4* __restrict__ feat,   // (N, 128) float4
    const int*    __restrict__ labels, // (N,)
    const int*    __restrict__ ignore_ptr,
    int N)
{
    __shared__ float4 ssum[NUM_C * A4];  // 38912 B -> 4 blocks/SM resident
    __shared__ float  scnt[4][NUM_C];    // per-warp count buckets

    const int t    = threadIdx.x;
    const int warp = t >> 5;
    const int lane = t & 31;

    #pragma unroll
    for (int i = t; i < NUM_C * A4; i += TPB1)
        ssum[i] = make_float4(0.f, 0.f, 0.f, 0.f);
    for (int i = t; i < 4 * NUM_C; i += TPB1)
        scnt[i / NUM_C][i % NUM_C] = 0.f;
    __syncthreads();

    const int ign  = *ignore_ptr;
    const int rows = (N + GRID1 - 1) / GRID1;
    const int r0   = blockIdx.x * rows;
    const int r1   = min(r0 + rows, N);

    const int nfull = (r1 - r0) >> 3;       // number of full 8-row batches

    int    labA[8], labB[8];
    float4 fA[8],   fB[8];

    if (nfull > 0) LOAD_BATCH(r0, labA, fA);

    int cch = 0;
    // Pipelined main loop: prefetch batch c+1 before consuming batch c.
    for (; cch + 2 < nfull; cch += 2) {
        LOAD_BATCH(r0 + (cch + 1) * 8, labB, fB);
        RMW_BATCH(labA, fA);
        LOAD_BATCH(r0 + (cch + 2) * 8, labA, fA);
        RMW_BATCH(labB, fB);
    }
    if (nfull > 0) {
        if (cch + 1 < nfull) {
            LOAD_BATCH(r0 + (cch + 1) * 8, labB, fB);
            RMW_BATCH(labA, fA);
            RMW_BATCH(labB, fB);
        } else {
            RMW_BATCH(labA, fA);
        }
    }
    // scalar tail
    for (int r = r0 + nfull * 8; r < r1; r++) {
        const int lab = __ldg(&labels[r]);
        if (lab != ign) {
            float4 f = feat[(size_t)r * A4 + t];
            const int idx = lab * A4 + t;
            float4 s = ssum[idx];
            s.x += f.x; s.y += f.y; s.z += f.z; s.w += f.w;
            ssum[idx] = s;
            if (t == 0) scnt[0][lab] += 1.f;
        }
    }
    __syncthreads();

    float4* pout = reinterpret_cast<float4*>(g_psums) + (size_t)blockIdx.x * NUM_C * A4;
    #pragma unroll
    for (int i = t; i < NUM_C * A4; i += TPB1)
        pout[i] = ssum[i];
    if (t < NUM_C)
        g_pcnts[blockIdx.x * NUM_C + t] =
            scnt[0][t] + scnt[1][t] + scnt[2][t] + scnt[3][t];
}

// grid (NUM_C, 16) x 512 threads. Block = (class c, 32-channel group).
// Thread t: a4 = t&7 (float4 channel), gp = t>>3 (one of 64 g-partitions).
// 304 blocks (~2/SM), 9 fixed loads + 1 predicated per thread.
__global__ void __launch_bounds__(512) bars_finalize_kernel(float* __restrict__ out)
{
    const int c    = blockIdx.x;
    const int agrp = blockIdx.y;
    const int t    = threadIdx.x;
    const int a4   = t & 7;     // 0..7
    const int gp   = t >> 3;    // 0..63
    const int warp = t >> 5;
    const int lane = t & 31;

    __shared__ float4 red[512];      // [gp][a4]
    __shared__ float  wcnt[16];      // per-warp count partials

    const float4* ps = reinterpret_cast<const float4*>(g_psums);
    const size_t stride = (size_t)NUM_C * A4;              // float4 per g-slab
    const size_t off    = (size_t)c * A4 + agrp * 8 + a4;  // float4 within slab

    // ---- per-class count, fully parallel (each thread <=2 loads) ----
    {
        const int g0 = warp * 32 + lane;                   // 0..511
        float cl = g_pcnts[g0 * NUM_C + c];
        if (g0 + 512 < GRID1) cl += g_pcnts[(g0 + 512) * NUM_C + c];
        #pragma unroll
        for (int o = 16; o > 0; o >>= 1)
            cl += __shfl_down_sync(0xFFFFFFFFu, cl, o);
        if (lane == 0) wcnt[warp] = cl;
    }

    // ---- main partial-sum reduction: g = gp + 64*k, k = 0..8 (+1 pred) ----
    float4 acc0 = make_float4(0.f, 0.f, 0.f, 0.f);
    float4 acc1 = make_float4(0.f, 0.f, 0.f, 0.f);
    float4 acc2 = make_float4(0.f, 0.f, 0.f, 0.f);
    const float4* base = ps + off + (size_t)gp * stride;
    #pragma unroll
    for (int k = 0; k < 9; k += 3) {
        float4 v0 = base[(size_t)(k + 0) * 64 * stride];
        float4 v1 = base[(size_t)(k + 1) * 64 * stride];
        float4 v2 = base[(size_t)(k + 2) * 64 * stride];
        acc0.x += v0.x; acc0.y += v0.y; acc0.z += v0.z; acc0.w += v0.w;
        acc1.x += v1.x; acc1.y += v1.y; acc1.z += v1.z; acc1.w += v1.w;
        acc2.x += v2.x; acc2.y += v2.y; acc2.z += v2.z; acc2.w += v2.w;
    }
    if (gp < GRID1 - 9 * 64) {                 // slab g = gp + 576 (gp < 16)
        float4 v = base[(size_t)9 * 64 * stride];
        acc0.x += v.x; acc0.y += v.y; acc0.z += v.z; acc0.w += v.w;
    }
    acc0.x += acc1.x + acc2.x;
    acc0.y += acc1.y + acc2.y;
    acc0.z += acc1.z + acc2.z;
    acc0.w += acc1.w + acc2.w;
    red[gp * 8 + a4] = acc0;
    __syncthreads();

    // Fold 64 g-partitions -> 1.
    #pragma unroll
    for (int s = 32; s > 0; s >>= 1) {
        if (gp < s) {
            float4 a = red[gp * 8 + a4];
            float4 b = red[(gp + s) * 8 + a4];
            a.x += b.x; a.y += b.y; a.z += b.z; a.w += b.w;
            red[gp * 8 + a4] = a;
        }
        __syncthreads();
    }

    if (t < 8) {
        float cnt = 0.f;
        #pragma unroll
        for (int w = 0; w < 16; w++) cnt += wcnt[w];
        const float inv = 1.f / ((cnt == 0.f) ? 1.f : cnt);
        float4 sum = red[a4];
        float4 mean = make_float4(sum.x * inv, sum.y * inv, sum.z * inv, sum.w * inv);

        float4* out4 = reinterpret_cast<float4*>(out);
        const int oidx = c * A4 + agrp * 8 + a4;
        out4[oidx] = mean;                                         // mean (C, A)
        out4[NUM_C * A4 + oidx] = make_float4(cnt, cnt, cnt, cnt); // sum_weight
        if (t == 0 && agrp == 0)
            out[2 * NUM_C * NUM_A + c] = cnt;                      // class_dist (C,)
    }
}

extern "C" void kernel_launch(void* const* d_in, const int* in_sizes, int n_in,
                              void* d_out, int out_size)
{
    const float4* feat   = (const float4*)d_in[0];
    const int*    labels = (const int*)d_in[1];
    const int*    ign    = (const int*)d_in[2];
    float*        out    = (float*)d_out;

    const int N = in_sizes[0] / NUM_A;

    bars_accum_kernel<<<GRID1, TPB1>>>(feat, labels, ign, N);
    bars_finalize_kernel<<<dim3(NUM_C, 16), 512>>>(out);
}

// round 6
// speedup vs baseline: 1.2772x; 1.0300x over previous
#include <cuda_runtime.h>

#define NUM_C 19
#define NUM_A 512            // feature channels
#define A4 (NUM_A / 4)       // float4 per row = 128
#define GRID1 148            // 1 block per SM -> no cross-CTA L1tex contention
#define TPB1 512             // 4 warpgroups of 128 threads
#define CPAD 20              // padded class stride for count buckets

// Per-warpgroup replica layout inside dynamic smem:
//   float4 ssum[4][NUM_C * A4]   (155648 B)
//   float  scnt[16][CPAD]        (1280 B)
#define SMEM_SSUM_F4 (4 * NUM_C * A4)
#define SMEM_BYTES   (SMEM_SSUM_F4 * 16 + 16 * CPAD * 4)

// Deterministic partial-sum scratch (no device-side allocation allowed).
__device__ float g_psums[(size_t)GRID1 * NUM_C * NUM_A]; // [g][c][a]  ~5.8 MB
__device__ float g_pcnts[GRID1 * NUM_C];                 // [g][c]

// ---- 8-row batch helpers (software pipeline) ----
#define LOAD_BATCH(RR, LAB, F)                                              \
    do {                                                                    \
        _Pragma("unroll")                                                   \
        for (int j = 0; j < 8; j++) LAB[j] = __ldg(&labels[(RR) + j]);      \
        _Pragma("unroll")                                                   \
        for (int j = 0; j < 8; j++)                                         \
            if (LAB[j] != ign)                                              \
                F[j] = feat[(size_t)((RR) + j) * A4 + tt];                  \
    } while (0)

#define RMW_BATCH(LAB, F)                                                   \
    do {                                                                    \
        _Pragma("unroll")                                                   \
        for (int j = 0; j < 8; j++) {                                       \
            if (LAB[j] != ign) {                                            \
                const int idx = LAB[j] * A4 + tt;                           \
                float4 s = ssum[idx];                                       \
                s.x += F[j].x; s.y += F[j].y; s.z += F[j].z; s.w += F[j].w; \
                ssum[idx] = s;                                              \
            }                                                               \
        }                                                                   \
        if (lane == 0) {                                                    \
            _Pragma("unroll")                                               \
            for (int j = 0; j < 2; j++) {                                   \
                const int jj = wgw * 2 + j;                                 \
                if (LAB[jj] != ign) scnt[warp * CPAD + LAB[jj]] += 1.f;     \
            }                                                               \
        }                                                                   \
    } while (0)

__global__ void __launch_bounds__(TPB1, 1) bars_accum_kernel(
    const float4* __restrict__ feat,   // (N, 128) float4
    const int*    __restrict__ labels, // (N,)
    const int*    __restrict__ ignore_ptr,
    int N)
{
    extern __shared__ float4 smem4[];
    const int t    = threadIdx.x;
    const int wg   = t >> 7;        // warpgroup 0..3
    const int tt   = t & 127;       // float4 channel within warpgroup
    const int warp = t >> 5;        // 0..15
    const int wgw  = warp & 3;      // warp within warpgroup
    const int lane = t & 31;

    float4* ssum = smem4 + (size_t)wg * (NUM_C * A4);     // this wg's replica
    float*  scnt = (float*)(smem4 + SMEM_SSUM_F4);        // [16][CPAD]

    #pragma unroll
    for (int i = t; i < SMEM_SSUM_F4; i += TPB1)
        smem4[i] = make_float4(0.f, 0.f, 0.f, 0.f);
    if (t < 16 * CPAD) scnt[t] = 0.f;
    __syncthreads();

    const int ign   = *ignore_ptr;
    const int rowsb = (N + GRID1 - 1) / GRID1;
    const int r0b   = blockIdx.x * rowsb;
    const int r1b   = min(r0b + rowsb, N);

    // split block rows into 4 contiguous warpgroup chunks
    const int nb    = r1b - r0b;
    const int chunk = (nb + 3) >> 2;
    const int r0    = min(r0b + wg * chunk, r1b);
    const int r1    = min(r0 + chunk, r1b);

    const int nfull = (r1 - r0) >> 3;       // full 8-row batches

    int    labA[8], labB[8];
    float4 fA[8],   fB[8];

    if (nfull > 0) LOAD_BATCH(r0, labA, fA);

    int b = 0;
    // Pipelined main loop: prefetch batch b+1 before consuming batch b.
    for (; b + 2 < nfull; b += 2) {
        LOAD_BATCH(r0 + (b + 1) * 8, labB, fB);
        RMW_BATCH(labA, fA);
        LOAD_BATCH(r0 + (b + 2) * 8, labA, fA);
        RMW_BATCH(labB, fB);
    }
    if (nfull > 0) {
        if (b + 1 < nfull) {
            LOAD_BATCH(r0 + (b + 1) * 8, labB, fB);
            RMW_BATCH(labA, fA);
            RMW_BATCH(labB, fB);
        } else {
            RMW_BATCH(labA, fA);
        }
    }
    // scalar tail (counted once per warpgroup by its thread 0)
    for (int r = r0 + nfull * 8; r < r1; r++) {
        const int lab = __ldg(&labels[r]);
        if (lab != ign) {
            float4 f = feat[(size_t)r * A4 + tt];
            const int idx = lab * A4 + tt;
            float4 s = ssum[idx];
            s.x += f.x; s.y += f.y; s.z += f.z; s.w += f.w;
            ssum[idx] = s;
            if (tt == 0) scnt[(wg * 4) * CPAD + lab] += 1.f;
        }
    }
    __syncthreads();

    // Reduce the 4 warpgroup replicas and store one slab per block.
    float4* pout = reinterpret_cast<float4*>(g_psums) + (size_t)blockIdx.x * NUM_C * A4;
    #pragma unroll
    for (int i = t; i < NUM_C * A4; i += TPB1) {
        float4 a = smem4[i];
        float4 bb = smem4[i + NUM_C * A4];
        float4 c4 = smem4[i + 2 * NUM_C * A4];
        float4 d = smem4[i + 3 * NUM_C * A4];
        a.x = (a.x + bb.x) + (c4.x + d.x);
        a.y = (a.y + bb.y) + (c4.y + d.y);
        a.z = (a.z + bb.z) + (c4.z + d.z);
        a.w = (a.w + bb.w) + (c4.w + d.w);
        pout[i] = a;
    }
    if (t < NUM_C) {
        float cl = 0.f;
        #pragma unroll
        for (int w = 0; w < 16; w++) cl += scnt[w * CPAD + t];
        g_pcnts[blockIdx.x * NUM_C + t] = cl;
    }
}

// grid (NUM_C, 8) x 256 threads. Block = (class c, 16-float4 channel group).
// Thread t: a4 = t&15, gp = t>>4 (16 g-partitions). 9 fixed + 1 predicated
// loads per thread over the 148 slabs.
__global__ void __launch_bounds__(256) bars_finalize_kernel(float* __restrict__ out)
{
    const int c    = blockIdx.x;
    const int agrp = blockIdx.y;
    const int t    = threadIdx.x;
    const int a4   = t & 15;    // 0..15
    const int gp   = t >> 4;    // 0..15
    const int warp = t >> 5;    // 0..7
    const int lane = t & 31;

    __shared__ float4 red[256];      // [gp][a4]
    __shared__ float  wcnt[8];       // per-warp count partials

    const float4* ps = reinterpret_cast<const float4*>(g_psums);
    const size_t stride = (size_t)NUM_C * A4;               // float4 per g-slab
    const size_t off    = (size_t)c * A4 + agrp * 16 + a4;  // float4 within slab

    // ---- per-class count (11 KB table, L2-hot; <=1 load per thread) ----
    {
        const int g0 = warp * 32 + lane;                    // 0..255
        float cl = (g0 < GRID1) ? g_pcnts[g0 * NUM_C + c] : 0.f;
        #pragma unroll
        for (int o = 16; o > 0; o >>= 1)
            cl += __shfl_down_sync(0xFFFFFFFFu, cl, o);
        if (lane == 0) wcnt[warp] = cl;
    }

    // ---- main partial-sum reduction: g = gp + 16*k, k = 0..8 (+1 pred) ----
    float4 acc0 = make_float4(0.f, 0.f, 0.f, 0.f);
    float4 acc1 = make_float4(0.f, 0.f, 0.f, 0.f);
    float4 acc2 = make_float4(0.f, 0.f, 0.f, 0.f);
    const float4* base = ps + off + (size_t)gp * stride;
    #pragma unroll
    for (int k = 0; k < 9; k += 3) {
        float4 v0 = base[(size_t)(k + 0) * 16 * stride];
        float4 v1 = base[(size_t)(k + 1) * 16 * stride];
        float4 v2 = base[(size_t)(k + 2) * 16 * stride];
        acc0.x += v0.x; acc0.y += v0.y; acc0.z += v0.z; acc0.w += v0.w;
        acc1.x += v1.x; acc1.y += v1.y; acc1.z += v1.z; acc1.w += v1.w;
        acc2.x += v2.x; acc2.y += v2.y; acc2.z += v2.z; acc2.w += v2.w;
    }
    if (gp < GRID1 - 9 * 16) {                 // slab g = 144 + gp (gp < 4)
        float4 v = base[(size_t)9 * 16 * stride];
        acc0.x += v.x; acc0.y += v.y; acc0.z += v.z; acc0.w += v.w;
    }
    acc0.x += acc1.x + acc2.x;
    acc0.y += acc1.y + acc2.y;
    acc0.z += acc1.z + acc2.z;
    acc0.w += acc1.w + acc2.w;
    red[gp * 16 + a4] = acc0;
    __syncthreads();

    // Fold 16 g-partitions -> 1.
    #pragma unroll
    for (int s = 8; s > 0; s >>= 1) {
        if (gp < s) {
            float4 a = red[gp * 16 + a4];
            float4 b = red[(gp + s) * 16 + a4];
            a.x += b.x; a.y += b.y; a.z += b.z; a.w += b.w;
            red[gp * 16 + a4] = a;
        }
        __syncthreads();
    }

    if (t < 16) {
        float cnt = 0.f;
        #pragma unroll
        for (int w = 0; w < 8; w++) cnt += wcnt[w];
        const float inv = 1.f / ((cnt == 0.f) ? 1.f : cnt);
        float4 sum = red[a4];
        float4 mean = make_float4(sum.x * inv, sum.y * inv, sum.z * inv, sum.w * inv);

        float4* out4 = reinterpret_cast<float4*>(out);
        const int oidx = c * A4 + agrp * 16 + a4;
        out4[oidx] = mean;                                         // mean (C, A)
        out4[NUM_C * A4 + oidx] = make_float4(cnt, cnt, cnt, cnt); // sum_weight
        if (t == 0 && agrp == 0)
            out[2 * NUM_C * NUM_A + c] = cnt;                      // class_dist (C,)
    }
}

extern "C" void kernel_launch(void* const* d_in, const int* in_sizes, int n_in,
                              void* d_out, int out_size)
{
    const float4* feat   = (const float4*)d_in[0];
    const int*    labels = (const int*)d_in[1];
    const int*    ign    = (const int*)d_in[2];
    float*        out    = (float*)d_out;

    const int N = in_sizes[0] / NUM_A;

    // Opt in to >48KB dynamic smem (host-side attribute set; not a stream op,
    // safe under graph capture, no allocation).
    cudaFuncSetAttribute(bars_accum_kernel,
                         cudaFuncAttributeMaxDynamicSharedMemorySize, SMEM_BYTES);

    bars_accum_kernel<<<GRID1, TPB1, SMEM_BYTES>>>(feat, labels, ign, N);
    bars_finalize_kernel<<<dim3(NUM_C, 8), 256>>>(out);
}

// round 7
// speedup vs baseline: 1.2886x; 1.0089x over previous
#include <cuda_runtime.h>

#define NUM_C 19
#define NUM_A 512            // feature channels
#define A4 (NUM_A / 4)       // float4 per row = 128
#define GRID1 148            // 1 block per SM -> no cross-CTA L1tex contention
#define TPB1 512             // 4 warpgroups of 128 threads
#define CPAD 20              // padded class stride for count buckets

// Per-warpgroup replica layout inside dynamic smem:
//   float4 ssum[4][NUM_C * A4]   (155648 B)
//   float  scnt[16][CPAD]        (1280 B)
#define SMEM_SSUM_F4 (4 * NUM_C * A4)
#define SMEM_BYTES   (SMEM_SSUM_F4 * 16 + 16 * CPAD * 4)

// Deterministic partial-sum scratch (no device-side allocation allowed).
__device__ float g_psums[(size_t)GRID1 * NUM_C * NUM_A]; // [g][c][a]  ~5.8 MB
__device__ float g_pcnts[GRID1 * NUM_C];                 // [g][c]

// ---- 8-row batch helpers (software pipeline) ----
#define LOAD_BATCH(RR, LAB, F)                                              \
    do {                                                                    \
        _Pragma("unroll")                                                   \
        for (int j = 0; j < 8; j++) LAB[j] = __ldg(&labels[(RR) + j]);      \
        _Pragma("unroll")                                                   \
        for (int j = 0; j < 8; j++)                                         \
            if (LAB[j] != ign)                                              \
                F[j] = feat[(size_t)((RR) + j) * A4 + tt];                  \
    } while (0)

#define RMW_BATCH(LAB, F)                                                   \
    do {                                                                    \
        _Pragma("unroll")                                                   \
        for (int j = 0; j < 8; j++) {                                       \
            if (LAB[j] != ign) {                                            \
                const int idx = LAB[j] * A4 + tt;                           \
                float4 s = ssum[idx];                                       \
                s.x += F[j].x; s.y += F[j].y; s.z += F[j].z; s.w += F[j].w; \
                ssum[idx] = s;                                              \
            }                                                               \
        }                                                                   \
        if (lane == 0) {                                                    \
            _Pragma("unroll")                                               \
            for (int j = 0; j < 2; j++) {                                   \
                const int jj = wgw * 2 + j;                                 \
                if (LAB[jj] != ign) scnt[warp * CPAD + LAB[jj]] += 1.f;     \
            }                                                               \
        }                                                                   \
    } while (0)

__global__ void __launch_bounds__(TPB1, 1) bars_accum_kernel(
    const float4* __restrict__ feat,   // (N, 128) float4
    const int*    __restrict__ labels, // (N,)
    const int*    __restrict__ ignore_ptr,
    int N)
{
    extern __shared__ float4 smem4[];
    const int t    = threadIdx.x;
    const int wg   = t >> 7;        // warpgroup 0..3
    const int tt   = t & 127;       // float4 channel within warpgroup
    const int warp = t >> 5;        // 0..15
    const int wgw  = warp & 3;      // warp within warpgroup
    const int lane = t & 31;

    float4* ssum = smem4 + (size_t)wg * (NUM_C * A4);     // this wg's replica
    float*  scnt = (float*)(smem4 + SMEM_SSUM_F4);        // [16][CPAD]

    #pragma unroll
    for (int i = t; i < SMEM_SSUM_F4; i += TPB1)
        smem4[i] = make_float4(0.f, 0.f, 0.f, 0.f);
    if (t < 16 * CPAD) scnt[t] = 0.f;
    __syncthreads();

    const int ign   = *ignore_ptr;
    const int rowsb = (N + GRID1 - 1) / GRID1;
    const int r0b   = blockIdx.x * rowsb;
    const int r1b   = min(r0b + rowsb, N);

    // split block rows into 4 contiguous warpgroup chunks
    const int nb    = r1b - r0b;
    const int chunk = (nb + 3) >> 2;
    const int r0    = min(r0b + wg * chunk, r1b);
    const int r1    = min(r0 + chunk, r1b);

    const int nfull = (r1 - r0) >> 3;       // full 8-row batches

    int    labA[8], labB[8];
    float4 fA[8],   fB[8];

    if (nfull > 0) LOAD_BATCH(r0, labA, fA);

    int b = 0;
    // Pipelined main loop: prefetch batch b+1 before consuming batch b.
    for (; b + 2 < nfull; b += 2) {
        LOAD_BATCH(r0 + (b + 1) * 8, labB, fB);
        RMW_BATCH(labA, fA);
        LOAD_BATCH(r0 + (b + 2) * 8, labA, fA);
        RMW_BATCH(labB, fB);
    }
    if (nfull > 0) {
        if (b + 1 < nfull) {
            LOAD_BATCH(r0 + (b + 1) * 8, labB, fB);
            RMW_BATCH(labA, fA);
            RMW_BATCH(labB, fB);
        } else {
            RMW_BATCH(labA, fA);
        }
    }
    // scalar tail (counted once per warpgroup by its thread 0)
    for (int r = r0 + nfull * 8; r < r1; r++) {
        const int lab = __ldg(&labels[r]);
        if (lab != ign) {
            float4 f = feat[(size_t)r * A4 + tt];
            const int idx = lab * A4 + tt;
            float4 s = ssum[idx];
            s.x += f.x; s.y += f.y; s.z += f.z; s.w += f.w;
            ssum[idx] = s;
            if (tt == 0) scnt[(wg * 4) * CPAD + lab] += 1.f;
        }
    }
    __syncthreads();

    // Reduce the 4 warpgroup replicas and store one slab per block.
    float4* pout = reinterpret_cast<float4*>(g_psums) + (size_t)blockIdx.x * NUM_C * A4;
    #pragma unroll
    for (int i = t; i < NUM_C * A4; i += TPB1) {
        float4 a = smem4[i];
        float4 bb = smem4[i + NUM_C * A4];
        float4 c4 = smem4[i + 2 * NUM_C * A4];
        float4 d = smem4[i + 3 * NUM_C * A4];
        a.x = (a.x + bb.x) + (c4.x + d.x);
        a.y = (a.y + bb.y) + (c4.y + d.y);
        a.z = (a.z + bb.z) + (c4.z + d.z);
        a.w = (a.w + bb.w) + (c4.w + d.w);
        pout[i] = a;
    }
    if (t < NUM_C) {
        float cl = 0.f;
        #pragma unroll
        for (int w = 0; w < 16; w++) cl += scnt[w * CPAD + t];
        g_pcnts[blockIdx.x * NUM_C + t] = cl;
    }
}

// grid (NUM_C, 8) x 512 threads. Block = (class c, 16-float4 channel group).
// Thread t: a4 = t&15, gp = t>>4 (32 g-partitions) -> 4 fixed + 1 predicated
// independent loads per thread; 16 warps/SM hide the L2-hit latency
// (5.8 MB scratch is L2-resident).
__global__ void __launch_bounds__(512) bars_finalize_kernel(float* __restrict__ out)
{
    const int c    = blockIdx.x;
    const int agrp = blockIdx.y;
    const int t    = threadIdx.x;
    const int a4   = t & 15;    // 0..15
    const int gp   = t >> 4;    // 0..31
    const int warp = t >> 5;    // 0..15
    const int lane = t & 31;

    __shared__ float4 red[512];      // [gp][a4]
    __shared__ float  wcnt[16];      // per-warp count partials

    const float4* ps = reinterpret_cast<const float4*>(g_psums);
    const size_t stride = (size_t)NUM_C * A4;               // float4 per g-slab
    const size_t off    = (size_t)c * A4 + agrp * 16 + a4;  // float4 within slab

    // ---- per-class count: one load per thread (148 <= 512), warp-reduced ----
    {
        float cl = (t < GRID1) ? g_pcnts[t * NUM_C + c] : 0.f;
        #pragma unroll
        for (int o = 16; o > 0; o >>= 1)
            cl += __shfl_down_sync(0xFFFFFFFFu, cl, o);
        if (lane == 0) wcnt[warp] = cl;
    }

    // ---- partial-sum reduction: g = gp + 32*k, k = 0..3, + pred g = 128+gp ----
    const float4* base = ps + off + (size_t)gp * stride;
    float4 v0 = base[0];
    float4 v1 = base[(size_t)32 * stride];
    float4 v2 = base[(size_t)64 * stride];
    float4 v3 = base[(size_t)96 * stride];
    float4 v4 = make_float4(0.f, 0.f, 0.f, 0.f);
    if (gp < GRID1 - 128)                       // gp < 20 -> slab 128+gp
        v4 = base[(size_t)128 * stride];

    float4 acc;
    acc.x = (v0.x + v1.x) + (v2.x + v3.x) + v4.x;
    acc.y = (v0.y + v1.y) + (v2.y + v3.y) + v4.y;
    acc.z = (v0.z + v1.z) + (v2.z + v3.z) + v4.z;
    acc.w = (v0.w + v1.w) + (v2.w + v3.w) + v4.w;
    red[gp * 16 + a4] = acc;
    __syncthreads();

    // Fold 32 g-partitions -> 1.
    #pragma unroll
    for (int s = 16; s > 0; s >>= 1) {
        if (gp < s) {
            float4 a = red[gp * 16 + a4];
            float4 b = red[(gp + s) * 16 + a4];
            a.x += b.x; a.y += b.y; a.z += b.z; a.w += b.w;
            red[gp * 16 + a4] = a;
        }
        __syncthreads();
    }

    if (t < 16) {
        float cnt = 0.f;
        #pragma unroll
        for (int w = 0; w < 16; w++) cnt += wcnt[w];
        const float inv = 1.f / ((cnt == 0.f) ? 1.f : cnt);
        float4 sum = red[a4];
        float4 mean = make_float4(sum.x * inv, sum.y * inv, sum.z * inv, sum.w * inv);

        float4* out4 = reinterpret_cast<float4*>(out);
        const int oidx = c * A4 + agrp * 16 + a4;
        out4[oidx] = mean;                                         // mean (C, A)
        out4[NUM_C * A4 + oidx] = make_float4(cnt, cnt, cnt, cnt); // sum_weight
        if (t == 0 && agrp == 0)
            out[2 * NUM_C * NUM_A + c] = cnt;                      // class_dist (C,)
    }
}

extern "C" void kernel_launch(void* const* d_in, const int* in_sizes, int n_in,
                              void* d_out, int out_size)
{
    const float4* feat   = (const float4*)d_in[0];
    const int*    labels = (const int*)d_in[1];
    const int*    ign    = (const int*)d_in[2];
    float*        out    = (float*)d_out;

    const int N = in_sizes[0] / NUM_A;

    // Opt in to >48KB dynamic smem (host-side attribute set; not a stream op,
    // safe under graph capture, no allocation).
    cudaFuncSetAttribute(bars_accum_kernel,
                         cudaFuncAttributeMaxDynamicSharedMemorySize, SMEM_BYTES);

    bars_accum_kernel<<<GRID1, TPB1, SMEM_BYTES>>>(feat, labels, ign, N);
    bars_finalize_kernel<<<dim3(NUM_C, 8), 512>>>(out);
}

// round 8
// speedup vs baseline: 1.3179x; 1.0227x over previous
#include <cuda_runtime.h>

#define NUM_C 19
#define NUM_A 512            // feature channels
#define A4 (NUM_A / 4)       // float4 per row = 128
#define GRID1 148            // accum blocks: 1 per SM
#define NFIN  (NUM_C * 8)    // finalize blocks: 152
#define TPB1 512             // 4 warpgroups of 128 threads
#define CPAD 20              // padded class stride for count buckets

// Per-warpgroup replica layout inside dynamic smem:
//   float4 ssum[4][NUM_C * A4]   (155648 B)
//   float  scnt[16][CPAD]        (1280 B)
#define SMEM_SSUM_F4 (4 * NUM_C * A4)
#define SMEM_BYTES   (SMEM_SSUM_F4 * 16 + 16 * CPAD * 4)

// Deterministic partial-sum scratch (no device-side allocation allowed).
__device__ float g_psums[(size_t)GRID1 * NUM_C * NUM_A]; // [g][c][a]  ~5.8 MB
__device__ float g_pcnts[GRID1 * NUM_C];                 // [g][c]
__device__ int   g_done;                                 // accum blocks finished
__device__ int   g_fin;                                  // finalize blocks past gate

// ---- 8-row batch helpers (software pipeline) ----
#define LOAD_BATCH(RR, LAB, F)                                              \
    do {                                                                    \
        const int4 L0 = __ldg((const int4*)&labels[(RR)]);                  \
        const int4 L1 = __ldg((const int4*)&labels[(RR) + 4]);              \
        LAB[0] = L0.x; LAB[1] = L0.y; LAB[2] = L0.z; LAB[3] = L0.w;         \
        LAB[4] = L1.x; LAB[5] = L1.y; LAB[6] = L1.z; LAB[7] = L1.w;         \
        _Pragma("unroll")                                                   \
        for (int j = 0; j < 8; j++)                                         \
            if (LAB[j] != ign)                                              \
                F[j] = __ldcs(&feat[(size_t)((RR) + j) * A4 + tt]);         \
    } while (0)

#define RMW_BATCH(LAB, F)                                                   \
    do {                                                                    \
        _Pragma("unroll")                                                   \
        for (int j = 0; j < 8; j++) {                                       \
            if (LAB[j] != ign) {                                            \
                const int idx = LAB[j] * A4 + tt;                           \
                float4 s = ssum[idx];                                       \
                s.x += F[j].x; s.y += F[j].y; s.z += F[j].z; s.w += F[j].w; \
                ssum[idx] = s;                                              \
            }                                                               \
        }                                                                   \
        if (lane == 0) {                                                    \
            _Pragma("unroll")                                               \
            for (int j = 0; j < 2; j++) {                                   \
                const int jj = wgw * 2 + j;                                 \
                if (LAB[jj] != ign) scnt[warp * CPAD + LAB[jj]] += 1.f;     \
            }                                                               \
        }                                                                   \
    } while (0)

__device__ __forceinline__ void accum_part(
    const float4* __restrict__ feat,
    const int*    __restrict__ labels,
    const int*    __restrict__ ignore_ptr,
    int N, float4* smem4)
{
    const int t    = threadIdx.x;
    const int wg   = t >> 7;        // warpgroup 0..3
    const int tt   = t & 127;       // float4 channel within warpgroup
    const int warp = t >> 5;        // 0..15
    const int wgw  = warp & 3;      // warp within warpgroup
    const int lane = t & 31;

    float4* ssum = smem4 + (size_t)wg * (NUM_C * A4);     // this wg's replica
    float*  scnt = (float*)(smem4 + SMEM_SSUM_F4);        // [16][CPAD]

    #pragma unroll
    for (int i = t; i < SMEM_SSUM_F4; i += TPB1)
        smem4[i] = make_float4(0.f, 0.f, 0.f, 0.f);
    if (t < 16 * CPAD) scnt[t] = 0.f;
    __syncthreads();

    const int ign   = *ignore_ptr;
    // rows per block rounded to 32 so warpgroup chunks stay 8-aligned (int4 labels)
    const int rowsb = (((N + GRID1 - 1) / GRID1) + 31) & ~31;
    const int r0b   = blockIdx.x * rowsb;
    const int r1b   = min(r0b + rowsb, N);

    const int nb    = max(r1b - r0b, 0);
    int chunk = (nb + 3) >> 2;
    chunk = (chunk + 7) & ~7;                             // 8-aligned
    const int r0    = min(r0b + wg * chunk, r1b);
    const int r1    = min(r0 + chunk, r1b);

    const int nfull = (r1 - r0) >> 3;       // full 8-row batches

    int    labA[8], labB[8];
    float4 fA[8],   fB[8];

    if (nfull > 0) LOAD_BATCH(r0, labA, fA);

    int b = 0;
    // Pipelined main loop: prefetch batch b+1 before consuming batch b.
    for (; b + 2 < nfull; b += 2) {
        LOAD_BATCH(r0 + (b + 1) * 8, labB, fB);
        RMW_BATCH(labA, fA);
        LOAD_BATCH(r0 + (b + 2) * 8, labA, fA);
        RMW_BATCH(labB, fB);
    }
    if (nfull > 0) {
        if (b + 1 < nfull) {
            LOAD_BATCH(r0 + (b + 1) * 8, labB, fB);
            RMW_BATCH(labA, fA);
            RMW_BATCH(labB, fB);
        } else {
            RMW_BATCH(labA, fA);
        }
    }
    // scalar tail
    for (int r = r0 + nfull * 8; r < r1; r++) {
        const int lab = __ldg(&labels[r]);
        if (lab != ign) {
            float4 f = __ldcs(&feat[(size_t)r * A4 + tt]);
            const int idx = lab * A4 + tt;
            float4 s = ssum[idx];
            s.x += f.x; s.y += f.y; s.z += f.z; s.w += f.w;
            ssum[idx] = s;
            if (tt == 0) scnt[(wg * 4) * CPAD + lab] += 1.f;
        }
    }
    __syncthreads();

    // Reduce the 4 warpgroup replicas and store one slab per block.
    float4* pout = reinterpret_cast<float4*>(g_psums) + (size_t)blockIdx.x * NUM_C * A4;
    #pragma unroll
    for (int i = t; i < NUM_C * A4; i += TPB1) {
        float4 a = smem4[i];
        float4 bb = smem4[i + NUM_C * A4];
        float4 c4 = smem4[i + 2 * NUM_C * A4];
        float4 d = smem4[i + 3 * NUM_C * A4];
        a.x = (a.x + bb.x) + (c4.x + d.x);
        a.y = (a.y + bb.y) + (c4.y + d.y);
        a.z = (a.z + bb.z) + (c4.z + d.z);
        a.w = (a.w + bb.w) + (c4.w + d.w);
        pout[i] = a;
    }
    if (t < NUM_C) {
        float cl = 0.f;
        #pragma unroll
        for (int w = 0; w < 16; w++) cl += scnt[w * CPAD + t];
        g_pcnts[blockIdx.x * NUM_C + t] = cl;
    }
    __syncthreads();
    __threadfence();                       // release psums/pcnts
    if (t == 0) atomicAdd(&g_done, 1);
}

__device__ __forceinline__ void finalize_part(float* __restrict__ out, float4* smem4)
{
    const int fb   = blockIdx.x - GRID1;   // 0..151
    const int c    = fb >> 3;              // class
    const int agrp = fb & 7;               // 16-float4 channel group
    const int t    = threadIdx.x;
    const int a4   = t & 15;    // 0..15
    const int gp   = t >> 4;    // 0..31
    const int warp = t >> 5;    // 0..15
    const int lane = t & 31;

    float4* red = smem4;                   // [32][16]
    __shared__ float wcnt[16];

    // ---- gate: wait for all accum blocks ----
    if (t == 0) {
        while (atomicAdd(&g_done, 0) < GRID1)
            __nanosleep(256);
    }
    __syncthreads();
    __threadfence();                       // acquire psums/pcnts

    const float4* ps = reinterpret_cast<const float4*>(g_psums);
    const size_t stride = (size_t)NUM_C * A4;
    const size_t off    = (size_t)c * A4 + agrp * 16 + a4;

    // ---- per-class count: one load per thread, warp-reduced ----
    {
        float cl = (t < GRID1) ? g_pcnts[t * NUM_C + c] : 0.f;
        #pragma unroll
        for (int o = 16; o > 0; o >>= 1)
            cl += __shfl_down_sync(0xFFFFFFFFu, cl, o);
        if (lane == 0) wcnt[warp] = cl;
    }

    // ---- partial-sum reduction: g = gp + 32*k, k = 0..3, + pred g = 128+gp ----
    const float4* base = ps + off + (size_t)gp * stride;
    float4 v0 = base[0];
    float4 v1 = base[(size_t)32 * stride];
    float4 v2 = base[(size_t)64 * stride];
    float4 v3 = base[(size_t)96 * stride];
    float4 v4 = make_float4(0.f, 0.f, 0.f, 0.f);
    if (gp < GRID1 - 128)
        v4 = base[(size_t)128 * stride];

    float4 acc;
    acc.x = (v0.x + v1.x) + (v2.x + v3.x) + v4.x;
    acc.y = (v0.y + v1.y) + (v2.y + v3.y) + v4.y;
    acc.z = (v0.z + v1.z) + (v2.z + v3.z) + v4.z;
    acc.w = (v0.w + v1.w) + (v2.w + v3.w) + v4.w;
    red[gp * 16 + a4] = acc;
    __syncthreads();

    #pragma unroll
    for (int s = 16; s > 0; s >>= 1) {
        if (gp < s) {
            float4 a = red[gp * 16 + a4];
            float4 b = red[(gp + s) * 16 + a4];
            a.x += b.x; a.y += b.y; a.z += b.z; a.w += b.w;
            red[gp * 16 + a4] = a;
        }
        __syncthreads();
    }

    if (t < 16) {
        float cnt = 0.f;
        #pragma unroll
        for (int w = 0; w < 16; w++) cnt += wcnt[w];
        const float inv = 1.f / ((cnt == 0.f) ? 1.f : cnt);
        float4 sum = red[a4];
        float4 mean = make_float4(sum.x * inv, sum.y * inv, sum.z * inv, sum.w * inv);

        float4* out4 = reinterpret_cast<float4*>(out);
        const int oidx = c * A4 + agrp * 16 + a4;
        out4[oidx] = mean;                                         // mean (C, A)
        out4[NUM_C * A4 + oidx] = make_float4(cnt, cnt, cnt, cnt); // sum_weight
        if (t == 0 && agrp == 0)
            out[2 * NUM_C * NUM_A + c] = cnt;                      // class_dist (C,)
    }

    // ---- counter self-reset so graph replays start from zero ----
    if (t == 0) {
        const int v = atomicAdd(&g_fin, 1);
        if (v == NFIN - 1) {               // all finalize blocks passed the gate
            g_fin  = 0;
            g_done = 0;
            __threadfence();
        }
    }
}

__global__ void __launch_bounds__(TPB1, 1) bars_fused_kernel(
    const float4* __restrict__ feat,
    const int*    __restrict__ labels,
    const int*    __restrict__ ignore_ptr,
    int N, float* __restrict__ out)
{
    extern __shared__ float4 smem4[];
    if (blockIdx.x < GRID1)
        accum_part(feat, labels, ignore_ptr, N, smem4);
    else
        finalize_part(out, smem4);
}

extern "C" void kernel_launch(void* const* d_in, const int* in_sizes, int n_in,
                              void* d_out, int out_size)
{
    const float4* feat   = (const float4*)d_in[0];
    const int*    labels = (const int*)d_in[1];
    const int*    ign    = (const int*)d_in[2];
    float*        out    = (float*)d_out;

    const int N = in_sizes[0] / NUM_A;

    cudaFuncSetAttribute(bars_fused_kernel,
                         cudaFuncAttributeMaxDynamicSharedMemorySize, SMEM_BYTES);

    bars_fused_kernel<<<GRID1 + NFIN, TPB1, SMEM_BYTES>>>(feat, labels, ign, N, out);
}